// round 13
// baseline (speedup 1.0000x reference)
#include <cuda_runtime.h>
#include <cuda_fp16.h>
#include <cstdint>

#define NCTX 4096
#define DMODEL 2048

// ---------------- scratch (static device globals; no runtime alloc) ----------------
__device__ __half g_s[(size_t)NCTX * NCTX];                       // 32 MB approx scores (fp16)
__device__ __align__(256) __half g_xh[(size_t)NCTX * DMODEL];
__device__ __align__(256) __half g_xl[(size_t)NCTX * DMODEL];
__device__ __align__(256) __half g_wqh[(size_t)DMODEL * DMODEL];
__device__ __align__(256) __half g_wql[(size_t)DMODEL * DMODEL];
__device__ __align__(256) __half g_wvh[(size_t)DMODEL * DMODEL];
__device__ __align__(256) __half g_qh[(size_t)NCTX * DMODEL];
__device__ __align__(256) __half g_ql[(size_t)NCTX * DMODEL];
__device__ __align__(256) __half g_zh[(size_t)NCTX * DMODEL];

constexpr int BM = 128, BN = 128, BK = 32;
constexpr int TILE_B = BM * BK * 2;                 // 8192 B per matrix tile
constexpr int NSTAGE = 3;
constexpr int SMEM3 = NSTAGE * 4 * TILE_B;          // 96 KB (3-pass: Ah,Al,Bh,Bl)
constexpr int SMEM1 = NSTAGE * 2 * TILE_B;          // 48 KB (1-pass: Ah,Bh)

__device__ __forceinline__ uint32_t sm_addr(const void* p) {
    uint32_t a;
    asm("{ .reg .u64 t; cvta.to.shared.u64 t, %1; cvt.u32.u64 %0, t; }" : "=r"(a) : "l"(p));
    return a;
}
__device__ __forceinline__ void cpasync16(uint32_t s, const void* g) {
    asm volatile("cp.async.cg.shared.global [%0], [%1], 16;" :: "r"(s), "l"(g));
}
__device__ __forceinline__ void ldmx4(uint32_t& r0, uint32_t& r1, uint32_t& r2, uint32_t& r3,
                                      uint32_t a) {
    asm volatile("ldmatrix.sync.aligned.m8n8.x4.shared.b16 {%0,%1,%2,%3}, [%4];"
                 : "=r"(r0), "=r"(r1), "=r"(r2), "=r"(r3) : "r"(a));
}
__device__ __forceinline__ void mma16816(float* c, const uint32_t* a, const uint32_t* b) {
    asm volatile("mma.sync.aligned.m16n8k16.row.col.f32.f16.f16.f32 "
                 "{%0,%1,%2,%3}, {%4,%5,%6,%7}, {%8,%9}, {%0,%1,%2,%3};"
                 : "+f"(c[0]), "+f"(c[1]), "+f"(c[2]), "+f"(c[3])
                 : "r"(a[0]), "r"(a[1]), "r"(a[2]), "r"(a[3]), "r"(b[0]), "r"(b[1]));
}
// fp16-accumulator variant (screening only)
__device__ __forceinline__ void mma16816h(uint32_t* c, const uint32_t* a, const uint32_t* b) {
    asm volatile("mma.sync.aligned.m16n8k16.row.col.f16.f16.f16.f16 "
                 "{%0,%1}, {%2,%3,%4,%5}, {%6,%7}, {%0,%1};"
                 : "+r"(c[0]), "+r"(c[1])
                 : "r"(a[0]), "r"(a[1]), "r"(a[2]), "r"(a[3]), "r"(b[0]), "r"(b[1]));
}
__device__ __forceinline__ uint32_t swoff(int row, int j) {
    return row * 64 + ((j ^ ((row >> 1) & 3)) << 4);
}

// ============ 3-pass GEMM (q projection): 128 thr, warp tile 64x64, 2 CTAs/SM ============
__global__ __launch_bounds__(128, 2)
void tgemm3(const __half* __restrict__ Ah, const __half* __restrict__ Al,
            const __half* __restrict__ Bh, const __half* __restrict__ Bl,
            __half* __restrict__ Ch, __half* __restrict__ Cl,
            int K, int lda, int ldb, int ldc)
{
    const int bx = blockIdx.x, by = blockIdx.y;
    const int nC = K / BK;
    constexpr int STAGE_ = 4 * TILE_B;
    constexpr int OFF_AL = TILE_B, OFF_BH = 2 * TILE_B, OFF_BL = 3 * TILE_B;

    extern __shared__ __align__(1024) char smem[];
    const uint32_t sb = sm_addr(smem);

    const int tid = threadIdx.x;
    const int lane = tid & 31, wid = tid >> 5;
    const int wm = wid & 1, wn = wid >> 1;
    const int lrow = tid >> 1;
    const int pr   = tid & 1;
    const size_t arow = (size_t)(by * BM + lrow) * lda;
    const size_t brow = (size_t)(bx * BN + lrow) * ldb;

    float acc[4][8][4];
    #pragma unroll
    for (int i = 0; i < 4; i++)
        #pragma unroll
        for (int j = 0; j < 8; j++)
            #pragma unroll
            for (int r = 0; r < 4; r++) acc[i][j][r] = 0.f;

    auto issue = [&](int c) {
        const uint32_t s0 = sb + (c % NSTAGE) * STAGE_;
        const int kc = c * BK;
        #pragma unroll
        for (int r = 0; r < 2; r++) {
            const int row = lrow + r * 64;
            const size_t ga = arow + (size_t)r * 64 * lda + kc;
            const size_t gb = brow + (size_t)r * 64 * ldb + kc;
            #pragma unroll
            for (int jj = 0; jj < 2; jj++) {
                const int j = 2 * pr + jj;
                const uint32_t so = swoff(row, j);
                cpasync16(s0 + so,          Ah + ga + j * 8);
                cpasync16(s0 + OFF_AL + so, Al + ga + j * 8);
                cpasync16(s0 + OFF_BH + so, Bh + gb + j * 8);
                cpasync16(s0 + OFF_BL + so, Bl + gb + j * 8);
            }
        }
    };

    issue(0); asm volatile("cp.async.commit_group;");
    issue(1); asm volatile("cp.async.commit_group;");

    for (int c = 0; c < nC; c++) {
        asm volatile("cp.async.wait_group 1;");
        __syncthreads();
        if (c + 2 < nC) issue(c + 2);
        asm volatile("cp.async.commit_group;");

        const uint32_t s0 = sb + (c % NSTAGE) * STAGE_;
        #pragma unroll
        for (int ks = 0; ks < 2; ks++) {
            uint32_t a[4][4], b_h[8][2], b_l[8][2];
            #pragma unroll
            for (int i = 0; i < 4; i++) {
                const int row = wm * 64 + i * 16 + (lane & 15);
                const int ch  = 2 * ks + (lane >> 4);
                ldmx4(a[i][0], a[i][1], a[i][2], a[i][3], s0 + swoff(row, ch));
            }
            #pragma unroll
            for (int p = 0; p < 4; p++) {
                const int row = wn * 64 + p * 16 + (lane & 7) + ((lane & 16) >> 1);
                const int ch  = 2 * ks + ((lane >> 3) & 1);
                const uint32_t off = swoff(row, ch);
                uint32_t r0, r1, r2, r3;
                ldmx4(r0, r1, r2, r3, s0 + OFF_BH + off);
                b_h[2 * p][0] = r0; b_h[2 * p][1] = r1;
                b_h[2 * p + 1][0] = r2; b_h[2 * p + 1][1] = r3;
                ldmx4(r0, r1, r2, r3, s0 + OFF_BL + off);
                b_l[2 * p][0] = r0; b_l[2 * p][1] = r1;
                b_l[2 * p + 1][0] = r2; b_l[2 * p + 1][1] = r3;
            }
            #pragma unroll
            for (int i = 0; i < 4; i++)
                #pragma unroll
                for (int j = 0; j < 8; j++)
                    mma16816(acc[i][j], a[i], b_h[j]);
            #pragma unroll
            for (int i = 0; i < 4; i++)
                #pragma unroll
                for (int j = 0; j < 8; j++)
                    mma16816(acc[i][j], a[i], b_l[j]);
            #pragma unroll
            for (int i = 0; i < 4; i++) {
                const int row = wm * 64 + i * 16 + (lane & 15);
                const int ch  = 2 * ks + (lane >> 4);
                ldmx4(a[i][0], a[i][1], a[i][2], a[i][3], s0 + OFF_AL + swoff(row, ch));
            }
            #pragma unroll
            for (int i = 0; i < 4; i++)
                #pragma unroll
                for (int j = 0; j < 8; j++)
                    mma16816(acc[i][j], a[i], b_h[j]);
        }
    }

    const int r0 = by * BM + wm * 64 + (lane >> 2);
    const int c0 = bx * BN + wn * 64 + (lane & 3) * 2;
    #pragma unroll
    for (int i = 0; i < 4; i++)
        #pragma unroll
        for (int j = 0; j < 8; j++) {
            #pragma unroll
            for (int h = 0; h < 2; h++) {
                const float v0 = acc[i][j][2 * h], v1 = acc[i][j][2 * h + 1];
                const size_t o = (size_t)(r0 + i * 16 + 8 * h) * ldc + c0 + j * 8;
                __half h0 = __float2half_rn(v0), h1 = __float2half_rn(v1);
                __half l0 = __float2half_rn(v0 - __half2float(h0));
                __half l1 = __float2half_rn(v1 - __half2float(h1));
                *(__half2*)(Ch + o) = __halves2half2(h0, h1);
                *(__half2*)(Cl + o) = __halves2half2(l0, l1);
            }
        }
}

// ============ screening GEMM: fp16 accumulate, 256 thr, warp 64x32, triangular 1D grid ============
__global__ __launch_bounds__(256, 2)
void tgemm_screen(const __half* __restrict__ Ah, const __half* __restrict__ Bh,
                  __half* __restrict__ C, int K, int lda, int ldb, int ldc)
{
    // triangular decode: t -> (by, bx), bx <= by
    const int t = blockIdx.x;
    int by = (int)((sqrtf(8.f * (float)t + 1.f) - 1.f) * 0.5f);
    while ((by + 1) * (by + 2) / 2 <= t) by++;
    while (by * (by + 1) / 2 > t) by--;
    const int bx = t - by * (by + 1) / 2;

    const int nC = K / BK;
    constexpr int STAGE_ = 2 * TILE_B;
    constexpr int OFF_B = TILE_B;

    extern __shared__ __align__(1024) char smem[];
    const uint32_t sb = sm_addr(smem);

    const int tid = threadIdx.x;
    const int lane = tid & 31, wid = tid >> 5;
    const int wm = wid & 1, wn = wid >> 1;

    const int lrow = tid >> 1;
    const int ljb  = (tid & 1) * 2;
    const size_t arow = (size_t)(by * BM + lrow) * lda;
    const size_t brow = (size_t)(bx * BN + lrow) * ldb;

    uint32_t acc[4][4][2];
    #pragma unroll
    for (int i = 0; i < 4; i++)
        #pragma unroll
        for (int j = 0; j < 4; j++) { acc[i][j][0] = 0u; acc[i][j][1] = 0u; }

    auto issue = [&](int c) {
        const uint32_t s0 = sb + (c % NSTAGE) * STAGE_;
        const int kc = c * BK;
        #pragma unroll
        for (int jj = 0; jj < 2; jj++) {
            const int j = ljb + jj;
            const uint32_t so = swoff(lrow, j);
            cpasync16(s0 + so,         Ah + arow + kc + j * 8);
            cpasync16(s0 + OFF_B + so, Bh + brow + kc + j * 8);
        }
    };

    issue(0); asm volatile("cp.async.commit_group;");
    issue(1); asm volatile("cp.async.commit_group;");

    for (int c = 0; c < nC; c++) {
        asm volatile("cp.async.wait_group 1;");
        __syncthreads();
        if (c + 2 < nC) issue(c + 2);
        asm volatile("cp.async.commit_group;");

        const uint32_t s0 = sb + (c % NSTAGE) * STAGE_;
        #pragma unroll
        for (int ks = 0; ks < 2; ks++) {
            uint32_t a[4][4], b_h[4][2];
            #pragma unroll
            for (int i = 0; i < 4; i++) {
                const int row = wm * 64 + i * 16 + (lane & 15);
                const int ch  = 2 * ks + (lane >> 4);
                ldmx4(a[i][0], a[i][1], a[i][2], a[i][3], s0 + swoff(row, ch));
            }
            #pragma unroll
            for (int p = 0; p < 2; p++) {
                const int row = wn * 32 + p * 16 + (lane & 7) + ((lane & 16) >> 1);
                const int ch  = 2 * ks + ((lane >> 3) & 1);
                uint32_t r0, r1, r2, r3;
                ldmx4(r0, r1, r2, r3, s0 + OFF_B + swoff(row, ch));
                b_h[2 * p][0] = r0; b_h[2 * p][1] = r1;
                b_h[2 * p + 1][0] = r2; b_h[2 * p + 1][1] = r3;
            }
            #pragma unroll
            for (int i = 0; i < 4; i++)
                #pragma unroll
                for (int j = 0; j < 4; j++)
                    mma16816h(acc[i][j], a[i], b_h[j]);
        }
    }

    // epilogue: acc regs are packed half2 (c0,c1 row+0; c2,c3 row+8)
    const int r0 = by * BM + wm * 64 + (lane >> 2);
    const int c0 = bx * BN + wn * 32 + (lane & 3) * 2;
    #pragma unroll
    for (int i = 0; i < 4; i++)
        #pragma unroll
        for (int j = 0; j < 4; j++) {
            #pragma unroll
            for (int h = 0; h < 2; h++) {
                const size_t o = (size_t)(r0 + i * 16 + 8 * h) * ldc + c0 + j * 8;
                *(uint32_t*)(C + o) = acc[i][j][h];
            }
        }
}

// ============ 1-pass fp32-acc GEMM (output projection): 256 thr, warp 64x32 ============
__global__ __launch_bounds__(256, 2)
void tgemm1(const __half* __restrict__ Ah, const __half* __restrict__ Bh,
            float* __restrict__ Cf, int K, int lda, int ldb, int ldc)
{
    const int bx = blockIdx.x, by = blockIdx.y;
    const int nC = K / BK;
    constexpr int STAGE_ = 2 * TILE_B;
    constexpr int OFF_B = TILE_B;

    extern __shared__ __align__(1024) char smem[];
    const uint32_t sb = sm_addr(smem);

    const int tid = threadIdx.x;
    const int lane = tid & 31, wid = tid >> 5;
    const int wm = wid & 1, wn = wid >> 1;

    const int lrow = tid >> 1;
    const int ljb  = (tid & 1) * 2;
    const size_t arow = (size_t)(by * BM + lrow) * lda;
    const size_t brow = (size_t)(bx * BN + lrow) * ldb;

    float acc[4][4][4];
    #pragma unroll
    for (int i = 0; i < 4; i++)
        #pragma unroll
        for (int j = 0; j < 4; j++)
            #pragma unroll
            for (int r = 0; r < 4; r++) acc[i][j][r] = 0.f;

    auto issue = [&](int c) {
        const uint32_t s0 = sb + (c % NSTAGE) * STAGE_;
        const int kc = c * BK;
        #pragma unroll
        for (int jj = 0; jj < 2; jj++) {
            const int j = ljb + jj;
            const uint32_t so = swoff(lrow, j);
            cpasync16(s0 + so,         Ah + arow + kc + j * 8);
            cpasync16(s0 + OFF_B + so, Bh + brow + kc + j * 8);
        }
    };

    issue(0); asm volatile("cp.async.commit_group;");
    issue(1); asm volatile("cp.async.commit_group;");

    for (int c = 0; c < nC; c++) {
        asm volatile("cp.async.wait_group 1;");
        __syncthreads();
        if (c + 2 < nC) issue(c + 2);
        asm volatile("cp.async.commit_group;");

        const uint32_t s0 = sb + (c % NSTAGE) * STAGE_;
        #pragma unroll
        for (int ks = 0; ks < 2; ks++) {
            uint32_t a[4][4], b_h[4][2];
            #pragma unroll
            for (int i = 0; i < 4; i++) {
                const int row = wm * 64 + i * 16 + (lane & 15);
                const int ch  = 2 * ks + (lane >> 4);
                ldmx4(a[i][0], a[i][1], a[i][2], a[i][3], s0 + swoff(row, ch));
            }
            #pragma unroll
            for (int p = 0; p < 2; p++) {
                const int row = wn * 32 + p * 16 + (lane & 7) + ((lane & 16) >> 1);
                const int ch  = 2 * ks + ((lane >> 3) & 1);
                uint32_t r0, r1, r2, r3;
                ldmx4(r0, r1, r2, r3, s0 + OFF_B + swoff(row, ch));
                b_h[2 * p][0] = r0; b_h[2 * p][1] = r1;
                b_h[2 * p + 1][0] = r2; b_h[2 * p + 1][1] = r3;
            }
            #pragma unroll
            for (int i = 0; i < 4; i++)
                #pragma unroll
                for (int j = 0; j < 4; j++)
                    mma16816(acc[i][j], a[i], b_h[j]);
        }
    }

    const int r0 = by * BM + wm * 64 + (lane >> 2);
    const int c0 = bx * BN + wn * 32 + (lane & 3) * 2;
    #pragma unroll
    for (int i = 0; i < 4; i++)
        #pragma unroll
        for (int j = 0; j < 4; j++) {
            #pragma unroll
            for (int h = 0; h < 2; h++) {
                const size_t o = (size_t)(r0 + i * 16 + 8 * h) * ldc + c0 + j * 8;
                *(float2*)(Cf + o) = make_float2(acc[i][j][2 * h], acc[i][j][2 * h + 1]);
            }
        }
}

// ---------------- fused fp32 -> fp16 hi/lo splits (x, Wqk, Wov in one launch) ----------------
__global__ __launch_bounds__(256)
void splitk_all(const float* __restrict__ x,   __half* __restrict__ xh, __half* __restrict__ xl,
                const float* __restrict__ wq,  __half* __restrict__ wqh, __half* __restrict__ wql,
                const float* __restrict__ wv,  __half* __restrict__ wvh)
{
    const int nx = NCTX * DMODEL, nw = DMODEL * DMODEL;
    int i = (blockIdx.x * 256 + threadIdx.x) * 4;
    const float* in; __half* h; __half* l;
    if (i < nx)               { in = x;  h = xh;  l = xl;  }
    else if (i < nx + nw)     { in = wq; h = wqh; l = wql; i -= nx; }
    else if (i < nx + 2 * nw) { in = wv; h = wvh; l = nullptr; i -= nx + nw; }
    else return;

    float4 v = *(const float4*)(in + i);
    __half h0 = __float2half_rn(v.x), h1 = __float2half_rn(v.y);
    __half h2 = __float2half_rn(v.z), h3 = __float2half_rn(v.w);
    *(__half2*)(h + i)     = __halves2half2(h0, h1);
    *(__half2*)(h + i + 2) = __halves2half2(h2, h3);
    if (l) {
        __half l0 = __float2half_rn(v.x - __half2float(h0));
        __half l1 = __float2half_rn(v.y - __half2float(h1));
        __half l2 = __float2half_rn(v.z - __half2float(h2));
        __half l3 = __float2half_rn(v.w - __half2float(h3));
        *(__half2*)(l + i)     = __halves2half2(l0, l1);
        *(__half2*)(l + i + 2) = __halves2half2(l2, l3);
    }
}

// ---------------- reductions ----------------
__device__ __forceinline__ float warpMax(float v) {
    #pragma unroll
    for (int o = 16; o; o >>= 1) v = fmaxf(v, __shfl_xor_sync(0xffffffffu, v, o));
    return v;
}
__device__ __forceinline__ float warpSum(float v) {
    #pragma unroll
    for (int o = 16; o; o >>= 1) v += __shfl_xor_sync(0xffffffffu, v, o);
    return v;
}

// ---------------- fused screening softmax + exact rescore + AV ----------------
// Margin 20.0 covers 1-pass screening error (~0.05) + fp16 accumulate drift (~0.7)
// + fp16 storage rounding (~0.12) with >2x slack.
__global__ __launch_bounds__(256)
void softmax_av_fused(const __half* __restrict__ S, const __half* __restrict__ Qh,
                      const __half* __restrict__ Ql, const float* __restrict__ x,
                      __half* __restrict__ Zh, int N)
{
    const int row = blockIdx.x;
    const int len = row + 1;
    const __half* Srow = S + (size_t)row * N;
    const int tid = threadIdx.x;
    const int lane = tid & 31, wid = tid >> 5;

    __shared__ float red[8];
    __shared__ int scnt;
    __shared__ uint32_t cidx[NCTX];
    __shared__ float    csc[NCTX];
    __shared__ float    qs[DMODEL];
    if (tid == 0) scnt = 0;

    // A: approx row max
    float m = -3.4e38f;
    for (int j = tid; j < len; j += 256) m = fmaxf(m, __half2float(Srow[j]));
    m = warpMax(m);
    if (lane == 0) red[wid] = m;
    __syncthreads();
    float ma = red[0];
    #pragma unroll
    for (int w = 1; w < 8; w++) ma = fmaxf(ma, red[w]);
    __syncthreads();

    // B: collect candidates; approximate tail mass
    const float thr = ma - 20.0f;
    float tail = 0.f;
    for (int j = tid; j < len; j += 256) {
        const float v = __half2float(Srow[j]);
        if (v > thr) {
            const int slot = atomicAdd(&scnt, 1);
            cidx[slot] = j;
        } else {
            tail += __expf(v - ma);
        }
    }
    tail = warpSum(tail);
    if (lane == 0) red[wid] = tail;
    // C: q row into smem (fp32 = qh + ql)
    const __half* qhr = Qh + (size_t)row * DMODEL;
    const __half* qlr = Ql + (size_t)row * DMODEL;
    __syncthreads();
    float tsum = 0.f;
    #pragma unroll
    for (int w = 0; w < 8; w++) tsum += red[w];
    for (int k = tid; k < DMODEL; k += 256)
        qs[k] = __half2float(qhr[k]) + __half2float(qlr[k]);
    __syncthreads();

    // D: exact rescoring, one warp per candidate
    const int nc = scnt;
    for (int c = wid; c < nc; c += 8) {
        const float* xr = x + (size_t)cidx[c] * DMODEL;
        float p = 0.f;
        #pragma unroll 4
        for (int k = lane; k < DMODEL; k += 32) p = fmaf(qs[k], xr[k], p);
        p = warpSum(p);
        if (lane == 0) csc[c] = p;
    }
    __syncthreads();

    // E: exact max over candidates
    float mx = -3.4e38f;
    for (int c = tid; c < nc; c += 256) mx = fmaxf(mx, csc[c]);
    mx = warpMax(mx);
    if (lane == 0) red[wid] = mx;
    __syncthreads();
    float me = red[0];
    #pragma unroll
    for (int w = 1; w < 8; w++) me = fmaxf(me, red[w]);
    __syncthreads();

    // F: Z = exact candidate mass + rescaled approximate tail
    float zs = 0.f;
    for (int c = tid; c < nc; c += 256) zs += __expf(csc[c] - me);
    zs = warpSum(zs);
    if (lane == 0) red[wid] = zs;
    __syncthreads();
    float Z = tsum * __expf(ma - me);
    #pragma unroll
    for (int w = 0; w < 8; w++) Z += red[w];
    const float inv = 1.0f / Z;

    // G: weights into csc
    for (int c = tid; c < nc; c += 256) csc[c] = __expf(csc[c] - me) * inv;
    __syncthreads();

    // H: z = sum_j w_j * x_j (each thread owns 8 dims)
    float acc[8];
    #pragma unroll
    for (int r = 0; r < 8; r++) acc[r] = 0.f;
    const int d0 = tid * 8;
    for (int c = 0; c < nc; c++) {
        const float w = csc[c];
        const float* xr = x + (size_t)cidx[c] * DMODEL + d0;
        const float4 a = *(const float4*)xr;
        const float4 b = *(const float4*)(xr + 4);
        acc[0] = fmaf(w, a.x, acc[0]); acc[1] = fmaf(w, a.y, acc[1]);
        acc[2] = fmaf(w, a.z, acc[2]); acc[3] = fmaf(w, a.w, acc[3]);
        acc[4] = fmaf(w, b.x, acc[4]); acc[5] = fmaf(w, b.y, acc[5]);
        acc[6] = fmaf(w, b.z, acc[6]); acc[7] = fmaf(w, b.w, acc[7]);
    }

    __half* zh = Zh + (size_t)row * DMODEL + d0;
    #pragma unroll
    for (int r = 0; r < 8; r += 2)
        *(__half2*)(zh + r) = __halves2half2(__float2half_rn(acc[r]),
                                             __float2half_rn(acc[r + 1]));
}

// ---------------- host ----------------
extern "C" void kernel_launch(void* const* d_in, const int* in_sizes, int n_in,
                              void* d_out, int out_size)
{
    const float* x   = (const float*)d_in[0];
    const float* Wqk = (const float*)d_in[1];
    const float* Wov = (const float*)d_in[2];
    float* out = (float*)d_out;

    __half* s; cudaGetSymbolAddress((void**)&s, g_s);
    __half *xh, *xl, *wqh, *wql, *wvh, *qh, *ql, *zh;
    cudaGetSymbolAddress((void**)&xh,  g_xh);  cudaGetSymbolAddress((void**)&xl,  g_xl);
    cudaGetSymbolAddress((void**)&wqh, g_wqh); cudaGetSymbolAddress((void**)&wql, g_wql);
    cudaGetSymbolAddress((void**)&wvh, g_wvh);
    cudaGetSymbolAddress((void**)&qh,  g_qh);  cudaGetSymbolAddress((void**)&ql,  g_ql);
    cudaGetSymbolAddress((void**)&zh,  g_zh);

    cudaFuncSetAttribute(tgemm3, cudaFuncAttributeMaxDynamicSharedMemorySize, SMEM3);
    cudaFuncSetAttribute(tgemm_screen, cudaFuncAttributeMaxDynamicSharedMemorySize, SMEM1);
    cudaFuncSetAttribute(tgemm1, cudaFuncAttributeMaxDynamicSharedMemorySize, SMEM1);

    const int nx = NCTX * DMODEL, nw = DMODEL * DMODEL;
    const int ntot = nx + 2 * nw;

    // 0) all input splits in one launch
    splitk_all<<<ntot / 1024, 256>>>(x, xh, xl, Wqk, wqh, wql, Wov, wvh);

    // 1) q = x @ Wqk^T -> q hi/lo (3-pass, 4-warp 64x64 kernel)
    tgemm3<<<dim3(DMODEL / BN, NCTX / BM), 128, SMEM3>>>(
        xh, xl, wqh, wql, qh, ql, DMODEL, DMODEL, DMODEL, DMODEL);

    // 2) s~ = qh @ xh^T (fp16-acc screening, triangular 1D grid) -> fp16 scores
    const int ntri = (NCTX / BM) * (NCTX / BM + 1) / 2;    // 528
    tgemm_screen<<<ntri, 256, SMEM1>>>(qh, xh, s, DMODEL, DMODEL, DMODEL, NCTX);

    // 3) fused screening softmax + exact rescore + AV -> z (fp16)
    softmax_av_fused<<<NCTX, 256>>>(s, qh, ql, x, zh, NCTX);

    // 4) out = zh @ Wovh^T (1-pass fp32 acc) -> fp32 output
    tgemm1<<<dim3(DMODEL / BN, NCTX / BM), 256, SMEM1>>>(
        zh, wvh, out, DMODEL, DMODEL, DMODEL, DMODEL);
}

// round 14
// speedup vs baseline: 1.0132x; 1.0132x over previous
#include <cuda_runtime.h>
#include <cuda_fp16.h>
#include <cstdint>

#define NCTX 4096
#define DMODEL 2048

// ---------------- scratch (static device globals; no runtime alloc) ----------------
__device__ __half g_s[(size_t)NCTX * NCTX];                       // 32 MB approx scores (fp16)
__device__ __align__(256) __half g_xh[(size_t)NCTX * DMODEL];
__device__ __align__(256) __half g_xl[(size_t)NCTX * DMODEL];
__device__ __align__(256) __half g_wqh[(size_t)DMODEL * DMODEL];
__device__ __align__(256) __half g_wql[(size_t)DMODEL * DMODEL];
__device__ __align__(256) __half g_wvh[(size_t)DMODEL * DMODEL];
__device__ __align__(256) __half g_qh[(size_t)NCTX * DMODEL];
__device__ __align__(256) __half g_ql[(size_t)NCTX * DMODEL];
__device__ __align__(256) __half g_zh[(size_t)NCTX * DMODEL];

constexpr int BM = 128, BN = 128, BK = 32;
constexpr int TILE_B = BM * BK * 2;                 // 8192 B per matrix tile
constexpr int NSTAGE = 3;
constexpr int SMEM3 = NSTAGE * 4 * TILE_B;          // 96 KB (3-pass: Ah,Al,Bh,Bl)
constexpr int SMEM1 = NSTAGE * 2 * TILE_B;          // 48 KB (1-pass: Ah,Bh)

__device__ __forceinline__ uint32_t sm_addr(const void* p) {
    uint32_t a;
    asm("{ .reg .u64 t; cvta.to.shared.u64 t, %1; cvt.u32.u64 %0, t; }" : "=r"(a) : "l"(p));
    return a;
}
__device__ __forceinline__ void cpasync16(uint32_t s, const void* g) {
    asm volatile("cp.async.cg.shared.global [%0], [%1], 16;" :: "r"(s), "l"(g));
}
__device__ __forceinline__ void ldmx4(uint32_t& r0, uint32_t& r1, uint32_t& r2, uint32_t& r3,
                                      uint32_t a) {
    asm volatile("ldmatrix.sync.aligned.m8n8.x4.shared.b16 {%0,%1,%2,%3}, [%4];"
                 : "=r"(r0), "=r"(r1), "=r"(r2), "=r"(r3) : "r"(a));
}
__device__ __forceinline__ void mma16816(float* c, const uint32_t* a, const uint32_t* b) {
    asm volatile("mma.sync.aligned.m16n8k16.row.col.f32.f16.f16.f32 "
                 "{%0,%1,%2,%3}, {%4,%5,%6,%7}, {%8,%9}, {%0,%1,%2,%3};"
                 : "+f"(c[0]), "+f"(c[1]), "+f"(c[2]), "+f"(c[3])
                 : "r"(a[0]), "r"(a[1]), "r"(a[2]), "r"(a[3]), "r"(b[0]), "r"(b[1]));
}
// fp16-accumulator variant (screening only)
__device__ __forceinline__ void mma16816h(uint32_t* c, const uint32_t* a, const uint32_t* b) {
    asm volatile("mma.sync.aligned.m16n8k16.row.col.f16.f16.f16.f16 "
                 "{%0,%1}, {%2,%3,%4,%5}, {%6,%7}, {%0,%1};"
                 : "+r"(c[0]), "+r"(c[1])
                 : "r"(a[0]), "r"(a[1]), "r"(a[2]), "r"(a[3]), "r"(b[0]), "r"(b[1]));
}
__device__ __forceinline__ uint32_t swoff(int row, int j) {
    return row * 64 + ((j ^ ((row >> 1) & 3)) << 4);
}

// ============ 3-pass GEMM (q projection): 128 thr, warp tile 64x64, 2 CTAs/SM ============
__global__ __launch_bounds__(128, 2)
void tgemm3(const __half* __restrict__ Ah, const __half* __restrict__ Al,
            const __half* __restrict__ Bh, const __half* __restrict__ Bl,
            __half* __restrict__ Ch, __half* __restrict__ Cl,
            int K, int lda, int ldb, int ldc)
{
    const int bx = blockIdx.x, by = blockIdx.y;
    const int nC = K / BK;
    constexpr int STAGE_ = 4 * TILE_B;
    constexpr int OFF_AL = TILE_B, OFF_BH = 2 * TILE_B, OFF_BL = 3 * TILE_B;

    extern __shared__ __align__(1024) char smem[];
    const uint32_t sb = sm_addr(smem);

    const int tid = threadIdx.x;
    const int lane = tid & 31, wid = tid >> 5;
    const int wm = wid & 1, wn = wid >> 1;
    const int lrow = tid >> 1;
    const int pr   = tid & 1;
    const size_t arow = (size_t)(by * BM + lrow) * lda;
    const size_t brow = (size_t)(bx * BN + lrow) * ldb;

    float acc[4][8][4];
    #pragma unroll
    for (int i = 0; i < 4; i++)
        #pragma unroll
        for (int j = 0; j < 8; j++)
            #pragma unroll
            for (int r = 0; r < 4; r++) acc[i][j][r] = 0.f;

    auto issue = [&](int c) {
        const uint32_t s0 = sb + (c % NSTAGE) * STAGE_;
        const int kc = c * BK;
        #pragma unroll
        for (int r = 0; r < 2; r++) {
            const int row = lrow + r * 64;
            const size_t ga = arow + (size_t)r * 64 * lda + kc;
            const size_t gb = brow + (size_t)r * 64 * ldb + kc;
            #pragma unroll
            for (int jj = 0; jj < 2; jj++) {
                const int j = 2 * pr + jj;
                const uint32_t so = swoff(row, j);
                cpasync16(s0 + so,          Ah + ga + j * 8);
                cpasync16(s0 + OFF_AL + so, Al + ga + j * 8);
                cpasync16(s0 + OFF_BH + so, Bh + gb + j * 8);
                cpasync16(s0 + OFF_BL + so, Bl + gb + j * 8);
            }
        }
    };

    issue(0); asm volatile("cp.async.commit_group;");
    issue(1); asm volatile("cp.async.commit_group;");

    for (int c = 0; c < nC; c++) {
        asm volatile("cp.async.wait_group 1;");
        __syncthreads();
        if (c + 2 < nC) issue(c + 2);
        asm volatile("cp.async.commit_group;");

        const uint32_t s0 = sb + (c % NSTAGE) * STAGE_;
        #pragma unroll
        for (int ks = 0; ks < 2; ks++) {
            uint32_t a[4][4], b_h[8][2], b_l[8][2];
            #pragma unroll
            for (int i = 0; i < 4; i++) {
                const int row = wm * 64 + i * 16 + (lane & 15);
                const int ch  = 2 * ks + (lane >> 4);
                ldmx4(a[i][0], a[i][1], a[i][2], a[i][3], s0 + swoff(row, ch));
            }
            #pragma unroll
            for (int p = 0; p < 4; p++) {
                const int row = wn * 64 + p * 16 + (lane & 7) + ((lane & 16) >> 1);
                const int ch  = 2 * ks + ((lane >> 3) & 1);
                const uint32_t off = swoff(row, ch);
                uint32_t r0, r1, r2, r3;
                ldmx4(r0, r1, r2, r3, s0 + OFF_BH + off);
                b_h[2 * p][0] = r0; b_h[2 * p][1] = r1;
                b_h[2 * p + 1][0] = r2; b_h[2 * p + 1][1] = r3;
                ldmx4(r0, r1, r2, r3, s0 + OFF_BL + off);
                b_l[2 * p][0] = r0; b_l[2 * p][1] = r1;
                b_l[2 * p + 1][0] = r2; b_l[2 * p + 1][1] = r3;
            }
            #pragma unroll
            for (int i = 0; i < 4; i++)
                #pragma unroll
                for (int j = 0; j < 8; j++)
                    mma16816(acc[i][j], a[i], b_h[j]);
            #pragma unroll
            for (int i = 0; i < 4; i++)
                #pragma unroll
                for (int j = 0; j < 8; j++)
                    mma16816(acc[i][j], a[i], b_l[j]);
            #pragma unroll
            for (int i = 0; i < 4; i++) {
                const int row = wm * 64 + i * 16 + (lane & 15);
                const int ch  = 2 * ks + (lane >> 4);
                ldmx4(a[i][0], a[i][1], a[i][2], a[i][3], s0 + OFF_AL + swoff(row, ch));
            }
            #pragma unroll
            for (int i = 0; i < 4; i++)
                #pragma unroll
                for (int j = 0; j < 8; j++)
                    mma16816(acc[i][j], a[i], b_h[j]);
        }
    }

    const int r0 = by * BM + wm * 64 + (lane >> 2);
    const int c0 = bx * BN + wn * 64 + (lane & 3) * 2;
    #pragma unroll
    for (int i = 0; i < 4; i++)
        #pragma unroll
        for (int j = 0; j < 8; j++) {
            #pragma unroll
            for (int h = 0; h < 2; h++) {
                const float v0 = acc[i][j][2 * h], v1 = acc[i][j][2 * h + 1];
                const size_t o = (size_t)(r0 + i * 16 + 8 * h) * ldc + c0 + j * 8;
                __half h0 = __float2half_rn(v0), h1 = __float2half_rn(v1);
                __half l0 = __float2half_rn(v0 - __half2float(h0));
                __half l1 = __float2half_rn(v1 - __half2float(h1));
                *(__half2*)(Ch + o) = __halves2half2(h0, h1);
                *(__half2*)(Cl + o) = __halves2half2(l0, l1);
            }
        }
}

// ============ screening GEMM: fp16 accumulate, 256 thr, warp 64x32, triangular 1D grid ============
__global__ __launch_bounds__(256, 2)
void tgemm_screen(const __half* __restrict__ Ah, const __half* __restrict__ Bh,
                  __half* __restrict__ C, int K, int lda, int ldb, int ldc)
{
    const int t = blockIdx.x;
    int by = (int)((sqrtf(8.f * (float)t + 1.f) - 1.f) * 0.5f);
    while ((by + 1) * (by + 2) / 2 <= t) by++;
    while (by * (by + 1) / 2 > t) by--;
    const int bx = t - by * (by + 1) / 2;

    const int nC = K / BK;
    constexpr int STAGE_ = 2 * TILE_B;
    constexpr int OFF_B = TILE_B;

    extern __shared__ __align__(1024) char smem[];
    const uint32_t sb = sm_addr(smem);

    const int tid = threadIdx.x;
    const int lane = tid & 31, wid = tid >> 5;
    const int wm = wid & 1, wn = wid >> 1;

    const int lrow = tid >> 1;
    const int ljb  = (tid & 1) * 2;
    const size_t arow = (size_t)(by * BM + lrow) * lda;
    const size_t brow = (size_t)(bx * BN + lrow) * ldb;

    uint32_t acc[4][4][2];
    #pragma unroll
    for (int i = 0; i < 4; i++)
        #pragma unroll
        for (int j = 0; j < 4; j++) { acc[i][j][0] = 0u; acc[i][j][1] = 0u; }

    auto issue = [&](int c) {
        const uint32_t s0 = sb + (c % NSTAGE) * STAGE_;
        const int kc = c * BK;
        #pragma unroll
        for (int jj = 0; jj < 2; jj++) {
            const int j = ljb + jj;
            const uint32_t so = swoff(lrow, j);
            cpasync16(s0 + so,         Ah + arow + kc + j * 8);
            cpasync16(s0 + OFF_B + so, Bh + brow + kc + j * 8);
        }
    };

    issue(0); asm volatile("cp.async.commit_group;");
    issue(1); asm volatile("cp.async.commit_group;");

    for (int c = 0; c < nC; c++) {
        asm volatile("cp.async.wait_group 1;");
        __syncthreads();
        if (c + 2 < nC) issue(c + 2);
        asm volatile("cp.async.commit_group;");

        const uint32_t s0 = sb + (c % NSTAGE) * STAGE_;
        #pragma unroll
        for (int ks = 0; ks < 2; ks++) {
            uint32_t a[4][4], b_h[4][2];
            #pragma unroll
            for (int i = 0; i < 4; i++) {
                const int row = wm * 64 + i * 16 + (lane & 15);
                const int ch  = 2 * ks + (lane >> 4);
                ldmx4(a[i][0], a[i][1], a[i][2], a[i][3], s0 + swoff(row, ch));
            }
            #pragma unroll
            for (int p = 0; p < 2; p++) {
                const int row = wn * 32 + p * 16 + (lane & 7) + ((lane & 16) >> 1);
                const int ch  = 2 * ks + ((lane >> 3) & 1);
                uint32_t r0, r1, r2, r3;
                ldmx4(r0, r1, r2, r3, s0 + OFF_B + swoff(row, ch));
                b_h[2 * p][0] = r0; b_h[2 * p][1] = r1;
                b_h[2 * p + 1][0] = r2; b_h[2 * p + 1][1] = r3;
            }
            #pragma unroll
            for (int i = 0; i < 4; i++)
                #pragma unroll
                for (int j = 0; j < 4; j++)
                    mma16816h(acc[i][j], a[i], b_h[j]);
        }
    }

    const int r0 = by * BM + wm * 64 + (lane >> 2);
    const int c0 = bx * BN + wn * 32 + (lane & 3) * 2;
    #pragma unroll
    for (int i = 0; i < 4; i++)
        #pragma unroll
        for (int j = 0; j < 4; j++) {
            #pragma unroll
            for (int h = 0; h < 2; h++) {
                const size_t o = (size_t)(r0 + i * 16 + 8 * h) * ldc + c0 + j * 8;
                *(uint32_t*)(C + o) = acc[i][j][h];
            }
        }
}

// ============ 1-pass fp32-acc GEMM (output projection): 256 thr, warp 64x32 ============
__global__ __launch_bounds__(256, 2)
void tgemm1(const __half* __restrict__ Ah, const __half* __restrict__ Bh,
            float* __restrict__ Cf, int K, int lda, int ldb, int ldc)
{
    const int bx = blockIdx.x, by = blockIdx.y;
    const int nC = K / BK;
    constexpr int STAGE_ = 2 * TILE_B;
    constexpr int OFF_B = TILE_B;

    extern __shared__ __align__(1024) char smem[];
    const uint32_t sb = sm_addr(smem);

    const int tid = threadIdx.x;
    const int lane = tid & 31, wid = tid >> 5;
    const int wm = wid & 1, wn = wid >> 1;

    const int lrow = tid >> 1;
    const int ljb  = (tid & 1) * 2;
    const size_t arow = (size_t)(by * BM + lrow) * lda;
    const size_t brow = (size_t)(bx * BN + lrow) * ldb;

    float acc[4][4][4];
    #pragma unroll
    for (int i = 0; i < 4; i++)
        #pragma unroll
        for (int j = 0; j < 4; j++)
            #pragma unroll
            for (int r = 0; r < 4; r++) acc[i][j][r] = 0.f;

    auto issue = [&](int c) {
        const uint32_t s0 = sb + (c % NSTAGE) * STAGE_;
        const int kc = c * BK;
        #pragma unroll
        for (int jj = 0; jj < 2; jj++) {
            const int j = ljb + jj;
            const uint32_t so = swoff(lrow, j);
            cpasync16(s0 + so,         Ah + arow + kc + j * 8);
            cpasync16(s0 + OFF_B + so, Bh + brow + kc + j * 8);
        }
    };

    issue(0); asm volatile("cp.async.commit_group;");
    issue(1); asm volatile("cp.async.commit_group;");

    for (int c = 0; c < nC; c++) {
        asm volatile("cp.async.wait_group 1;");
        __syncthreads();
        if (c + 2 < nC) issue(c + 2);
        asm volatile("cp.async.commit_group;");

        const uint32_t s0 = sb + (c % NSTAGE) * STAGE_;
        #pragma unroll
        for (int ks = 0; ks < 2; ks++) {
            uint32_t a[4][4], b_h[4][2];
            #pragma unroll
            for (int i = 0; i < 4; i++) {
                const int row = wm * 64 + i * 16 + (lane & 15);
                const int ch  = 2 * ks + (lane >> 4);
                ldmx4(a[i][0], a[i][1], a[i][2], a[i][3], s0 + swoff(row, ch));
            }
            #pragma unroll
            for (int p = 0; p < 2; p++) {
                const int row = wn * 32 + p * 16 + (lane & 7) + ((lane & 16) >> 1);
                const int ch  = 2 * ks + ((lane >> 3) & 1);
                uint32_t r0, r1, r2, r3;
                ldmx4(r0, r1, r2, r3, s0 + OFF_B + swoff(row, ch));
                b_h[2 * p][0] = r0; b_h[2 * p][1] = r1;
                b_h[2 * p + 1][0] = r2; b_h[2 * p + 1][1] = r3;
            }
            #pragma unroll
            for (int i = 0; i < 4; i++)
                #pragma unroll
                for (int j = 0; j < 4; j++)
                    mma16816(acc[i][j], a[i], b_h[j]);
        }
    }

    const int r0 = by * BM + wm * 64 + (lane >> 2);
    const int c0 = bx * BN + wn * 32 + (lane & 3) * 2;
    #pragma unroll
    for (int i = 0; i < 4; i++)
        #pragma unroll
        for (int j = 0; j < 4; j++) {
            #pragma unroll
            for (int h = 0; h < 2; h++) {
                const size_t o = (size_t)(r0 + i * 16 + 8 * h) * ldc + c0 + j * 8;
                *(float2*)(Cf + o) = make_float2(acc[i][j][2 * h], acc[i][j][2 * h + 1]);
            }
        }
}

// ---------------- fused fp32 -> fp16 hi/lo splits ----------------
__global__ __launch_bounds__(256)
void splitk_all(const float* __restrict__ x,   __half* __restrict__ xh, __half* __restrict__ xl,
                const float* __restrict__ wq,  __half* __restrict__ wqh, __half* __restrict__ wql,
                const float* __restrict__ wv,  __half* __restrict__ wvh)
{
    const int nx = NCTX * DMODEL, nw = DMODEL * DMODEL;
    int i = (blockIdx.x * 256 + threadIdx.x) * 4;
    const float* in; __half* h; __half* l;
    if (i < nx)               { in = x;  h = xh;  l = xl;  }
    else if (i < nx + nw)     { in = wq; h = wqh; l = wql; i -= nx; }
    else if (i < nx + 2 * nw) { in = wv; h = wvh; l = nullptr; i -= nx + nw; }
    else return;

    float4 v = *(const float4*)(in + i);
    __half h0 = __float2half_rn(v.x), h1 = __float2half_rn(v.y);
    __half h2 = __float2half_rn(v.z), h3 = __float2half_rn(v.w);
    *(__half2*)(h + i)     = __halves2half2(h0, h1);
    *(__half2*)(h + i + 2) = __halves2half2(h2, h3);
    if (l) {
        __half l0 = __float2half_rn(v.x - __half2float(h0));
        __half l1 = __float2half_rn(v.y - __half2float(h1));
        __half l2 = __float2half_rn(v.z - __half2float(h2));
        __half l3 = __float2half_rn(v.w - __half2float(h3));
        *(__half2*)(l + i)     = __halves2half2(l0, l1);
        *(__half2*)(l + i + 2) = __halves2half2(l2, l3);
    }
}

// ---------------- reductions ----------------
__device__ __forceinline__ float warpMax(float v) {
    #pragma unroll
    for (int o = 16; o; o >>= 1) v = fmaxf(v, __shfl_xor_sync(0xffffffffu, v, o));
    return v;
}
__device__ __forceinline__ float warpSum(float v) {
    #pragma unroll
    for (int o = 16; o; o >>= 1) v += __shfl_xor_sync(0xffffffffu, v, o);
    return v;
}

// ---------------- fused screening softmax + exact rescore + AV ----------------
// Single-pass vectorized score read (2 x uint4 = 16 halves per thread), values
// cached in registers for the max + collect + tail phases. Margin 20.0 covers
// screening (1-pass fp16-acc) + fp16 storage error with >2x slack.
__global__ __launch_bounds__(256)
void softmax_av_fused(const __half* __restrict__ S, const __half* __restrict__ Qh,
                      const __half* __restrict__ Ql, const float* __restrict__ x,
                      __half* __restrict__ Zh, int N)
{
    const int row = blockIdx.x;
    const int len = row + 1;
    const __half* Srow = S + (size_t)row * N;
    const int tid = threadIdx.x;
    const int lane = tid & 31, wid = tid >> 5;

    __shared__ float red[8];
    __shared__ int scnt;
    __shared__ uint32_t cidx[NCTX];
    __shared__ float    csc[NCTX];
    __shared__ float    qs[DMODEL];
    if (tid == 0) scnt = 0;

    // A: single vectorized pass — load 2 chunks of 8 halves, cache as floats
    float vals[2][8];
    float m = -3.4e38f;
    #pragma unroll
    for (int k = 0; k < 2; k++) {
        const int base = tid * 8 + k * 2048;
        if (base < len) {
            const uint4 u = *(const uint4*)(Srow + base);
            const __half2* hp = (const __half2*)&u;
            #pragma unroll
            for (int e = 0; e < 4; e++) {
                const float2 f = __half22float2(hp[e]);
                vals[k][2 * e]     = (base + 2 * e     < len) ? f.x : -3.4e38f;
                vals[k][2 * e + 1] = (base + 2 * e + 1 < len) ? f.y : -3.4e38f;
            }
            #pragma unroll
            for (int e = 0; e < 8; e++) m = fmaxf(m, vals[k][e]);
        } else {
            #pragma unroll
            for (int e = 0; e < 8; e++) vals[k][e] = -3.4e38f;
        }
    }
    m = warpMax(m);
    if (lane == 0) red[wid] = m;
    __syncthreads();
    float ma = red[0];
    #pragma unroll
    for (int w = 1; w < 8; w++) ma = fmaxf(ma, red[w]);
    __syncthreads();

    // B: collect candidates + approximate tail mass from registers
    const float thr = ma - 20.0f;
    float tail = 0.f;
    #pragma unroll
    for (int k = 0; k < 2; k++) {
        #pragma unroll
        for (int e = 0; e < 8; e++) {
            const float v = vals[k][e];
            if (v > thr) {
                const int slot = atomicAdd(&scnt, 1);
                cidx[slot] = tid * 8 + k * 2048 + e;
            } else if (v > -1e37f) {
                tail += __expf(v - ma);
            }
        }
    }
    tail = warpSum(tail);
    if (lane == 0) red[wid] = tail;
    // C: q row into smem (fp32 = qh + ql)
    const __half* qhr = Qh + (size_t)row * DMODEL;
    const __half* qlr = Ql + (size_t)row * DMODEL;
    __syncthreads();
    float tsum = 0.f;
    #pragma unroll
    for (int w = 0; w < 8; w++) tsum += red[w];
    for (int k = tid; k < DMODEL; k += 256)
        qs[k] = __half2float(qhr[k]) + __half2float(qlr[k]);
    __syncthreads();

    // D: exact rescoring, one warp per candidate
    const int nc = scnt;
    for (int c = wid; c < nc; c += 8) {
        const float* xr = x + (size_t)cidx[c] * DMODEL;
        float p = 0.f;
        #pragma unroll 4
        for (int k = lane; k < DMODEL; k += 32) p = fmaf(qs[k], xr[k], p);
        p = warpSum(p);
        if (lane == 0) csc[c] = p;
    }
    __syncthreads();

    // E: exact max over candidates
    float mx = -3.4e38f;
    for (int c = tid; c < nc; c += 256) mx = fmaxf(mx, csc[c]);
    mx = warpMax(mx);
    if (lane == 0) red[wid] = mx;
    __syncthreads();
    float me = red[0];
    #pragma unroll
    for (int w = 1; w < 8; w++) me = fmaxf(me, red[w]);
    __syncthreads();

    // F: Z = exact candidate mass + rescaled approximate tail
    float zs = 0.f;
    for (int c = tid; c < nc; c += 256) zs += __expf(csc[c] - me);
    zs = warpSum(zs);
    if (lane == 0) red[wid] = zs;
    __syncthreads();
    float Z = tsum * __expf(ma - me);
    #pragma unroll
    for (int w = 0; w < 8; w++) Z += red[w];
    const float inv = 1.0f / Z;

    // G: weights into csc
    for (int c = tid; c < nc; c += 256) csc[c] = __expf(csc[c] - me) * inv;
    __syncthreads();

    // H: z = sum_j w_j * x_j (each thread owns 8 dims)
    float acc[8];
    #pragma unroll
    for (int r = 0; r < 8; r++) acc[r] = 0.f;
    const int d0 = tid * 8;
    for (int c = 0; c < nc; c++) {
        const float w = csc[c];
        const float* xr = x + (size_t)cidx[c] * DMODEL + d0;
        const float4 a = *(const float4*)xr;
        const float4 b = *(const float4*)(xr + 4);
        acc[0] = fmaf(w, a.x, acc[0]); acc[1] = fmaf(w, a.y, acc[1]);
        acc[2] = fmaf(w, a.z, acc[2]); acc[3] = fmaf(w, a.w, acc[3]);
        acc[4] = fmaf(w, b.x, acc[4]); acc[5] = fmaf(w, b.y, acc[5]);
        acc[6] = fmaf(w, b.z, acc[6]); acc[7] = fmaf(w, b.w, acc[7]);
    }

    __half* zh = Zh + (size_t)row * DMODEL + d0;
    #pragma unroll
    for (int r = 0; r < 8; r += 2)
        *(__half2*)(zh + r) = __halves2half2(__float2half_rn(acc[r]),
                                             __float2half_rn(acc[r + 1]));
}

// ---------------- host ----------------
extern "C" void kernel_launch(void* const* d_in, const int* in_sizes, int n_in,
                              void* d_out, int out_size)
{
    const float* x   = (const float*)d_in[0];
    const float* Wqk = (const float*)d_in[1];
    const float* Wov = (const float*)d_in[2];
    float* out = (float*)d_out;

    __half* s; cudaGetSymbolAddress((void**)&s, g_s);
    __half *xh, *xl, *wqh, *wql, *wvh, *qh, *ql, *zh;
    cudaGetSymbolAddress((void**)&xh,  g_xh);  cudaGetSymbolAddress((void**)&xl,  g_xl);
    cudaGetSymbolAddress((void**)&wqh, g_wqh); cudaGetSymbolAddress((void**)&wql, g_wql);
    cudaGetSymbolAddress((void**)&wvh, g_wvh);
    cudaGetSymbolAddress((void**)&qh,  g_qh);  cudaGetSymbolAddress((void**)&ql,  g_ql);
    cudaGetSymbolAddress((void**)&zh,  g_zh);

    cudaFuncSetAttribute(tgemm3, cudaFuncAttributeMaxDynamicSharedMemorySize, SMEM3);
    cudaFuncSetAttribute(tgemm_screen, cudaFuncAttributeMaxDynamicSharedMemorySize, SMEM1);
    cudaFuncSetAttribute(tgemm1, cudaFuncAttributeMaxDynamicSharedMemorySize, SMEM1);

    const int nx = NCTX * DMODEL, nw = DMODEL * DMODEL;
    const int ntot = nx + 2 * nw;

    // 0) all input splits in one launch
    splitk_all<<<ntot / 1024, 256>>>(x, xh, xl, Wqk, wqh, wql, Wov, wvh);

    // 1) q = x @ Wqk^T -> q hi/lo (3-pass, 4-warp 64x64 kernel)
    tgemm3<<<dim3(DMODEL / BN, NCTX / BM), 128, SMEM3>>>(
        xh, xl, wqh, wql, qh, ql, DMODEL, DMODEL, DMODEL, DMODEL);

    // 2) s~ = qh @ xh^T (fp16-acc screening, triangular 1D grid) -> fp16 scores
    const int ntri = (NCTX / BM) * (NCTX / BM + 1) / 2;    // 528
    tgemm_screen<<<ntri, 256, SMEM1>>>(qh, xh, s, DMODEL, DMODEL, DMODEL, NCTX);

    // 3) fused screening softmax + exact rescore + AV -> z (fp16)
    softmax_av_fused<<<NCTX, 256>>>(s, qh, ql, x, zh, NCTX);

    // 4) out = zh @ Wovh^T (1-pass fp32 acc) -> fp32 output
    tgemm1<<<dim3(DMODEL / BN, NCTX / BM), 256, SMEM1>>>(
        zh, wvh, out, DMODEL, DMODEL, DMODEL, DMODEL);
}

// round 15
// speedup vs baseline: 1.0808x; 1.0668x over previous
#include <cuda_runtime.h>
#include <cuda_fp16.h>
#include <cstdint>

#define NCTX 4096
#define DMODEL 2048

// ---------------- scratch (static device globals; no runtime alloc) ----------------
__device__ __half g_s[(size_t)NCTX * NCTX];                       // 32 MB approx scores (fp16)
__device__ __align__(256) __half g_xh[(size_t)NCTX * DMODEL];
__device__ __align__(256) __half g_xl[(size_t)NCTX * DMODEL];
__device__ __align__(256) __half g_wqh[(size_t)DMODEL * DMODEL];
__device__ __align__(256) __half g_wql[(size_t)DMODEL * DMODEL];
__device__ __align__(256) __half g_wvh[(size_t)DMODEL * DMODEL];
__device__ __align__(256) __half g_qh[(size_t)NCTX * DMODEL];
__device__ __align__(256) __half g_ql[(size_t)NCTX * DMODEL];
__device__ __align__(256) __half g_zh[(size_t)NCTX * DMODEL];

constexpr int BM = 128, BN = 128, BK = 32;
constexpr int TILE_B = BM * BK * 2;                 // 8192 B per matrix tile
constexpr int NSTAGE = 3;
constexpr int SMEM3 = NSTAGE * 4 * TILE_B;          // 96 KB (3-pass: Ah,Al,Bh,Bl)
constexpr int SMEM1 = NSTAGE * 2 * TILE_B;          // 48 KB (1-pass: Ah,Bh)

__device__ __forceinline__ uint32_t sm_addr(const void* p) {
    uint32_t a;
    asm("{ .reg .u64 t; cvta.to.shared.u64 t, %1; cvt.u32.u64 %0, t; }" : "=r"(a) : "l"(p));
    return a;
}
__device__ __forceinline__ void cpasync16(uint32_t s, const void* g) {
    asm volatile("cp.async.cg.shared.global [%0], [%1], 16;" :: "r"(s), "l"(g));
}
__device__ __forceinline__ void ldmx4(uint32_t& r0, uint32_t& r1, uint32_t& r2, uint32_t& r3,
                                      uint32_t a) {
    asm volatile("ldmatrix.sync.aligned.m8n8.x4.shared.b16 {%0,%1,%2,%3}, [%4];"
                 : "=r"(r0), "=r"(r1), "=r"(r2), "=r"(r3) : "r"(a));
}
__device__ __forceinline__ void mma16816(float* c, const uint32_t* a, const uint32_t* b) {
    asm volatile("mma.sync.aligned.m16n8k16.row.col.f32.f16.f16.f32 "
                 "{%0,%1,%2,%3}, {%4,%5,%6,%7}, {%8,%9}, {%0,%1,%2,%3};"
                 : "+f"(c[0]), "+f"(c[1]), "+f"(c[2]), "+f"(c[3])
                 : "r"(a[0]), "r"(a[1]), "r"(a[2]), "r"(a[3]), "r"(b[0]), "r"(b[1]));
}
// fp16-accumulator variant (screening only)
__device__ __forceinline__ void mma16816h(uint32_t* c, const uint32_t* a, const uint32_t* b) {
    asm volatile("mma.sync.aligned.m16n8k16.row.col.f16.f16.f16.f16 "
                 "{%0,%1}, {%2,%3,%4,%5}, {%6,%7}, {%0,%1};"
                 : "+r"(c[0]), "+r"(c[1])
                 : "r"(a[0]), "r"(a[1]), "r"(a[2]), "r"(a[3]), "r"(b[0]), "r"(b[1]));
}
__device__ __forceinline__ uint32_t swoff(int row, int j) {
    return row * 64 + ((j ^ ((row >> 1) & 3)) << 4);
}

// ============ 3-pass GEMM (q projection): 128 thr, warp tile 64x64, 2 CTAs/SM ============
__global__ __launch_bounds__(128, 2)
void tgemm3(const __half* __restrict__ Ah, const __half* __restrict__ Al,
            const __half* __restrict__ Bh, const __half* __restrict__ Bl,
            __half* __restrict__ Ch, __half* __restrict__ Cl,
            int K, int lda, int ldb, int ldc)
{
    const int bx = blockIdx.x, by = blockIdx.y;
    const int nC = K / BK;
    constexpr int STAGE_ = 4 * TILE_B;
    constexpr int OFF_AL = TILE_B, OFF_BH = 2 * TILE_B, OFF_BL = 3 * TILE_B;

    extern __shared__ __align__(1024) char smem[];
    const uint32_t sb = sm_addr(smem);

    const int tid = threadIdx.x;
    const int lane = tid & 31, wid = tid >> 5;
    const int wm = wid & 1, wn = wid >> 1;
    const int lrow = tid >> 1;
    const int pr   = tid & 1;
    const size_t arow = (size_t)(by * BM + lrow) * lda;
    const size_t brow = (size_t)(bx * BN + lrow) * ldb;

    float acc[4][8][4];
    #pragma unroll
    for (int i = 0; i < 4; i++)
        #pragma unroll
        for (int j = 0; j < 8; j++)
            #pragma unroll
            for (int r = 0; r < 4; r++) acc[i][j][r] = 0.f;

    auto issue = [&](int c) {
        const uint32_t s0 = sb + (c % NSTAGE) * STAGE_;
        const int kc = c * BK;
        #pragma unroll
        for (int r = 0; r < 2; r++) {
            const int row = lrow + r * 64;
            const size_t ga = arow + (size_t)r * 64 * lda + kc;
            const size_t gb = brow + (size_t)r * 64 * ldb + kc;
            #pragma unroll
            for (int jj = 0; jj < 2; jj++) {
                const int j = 2 * pr + jj;
                const uint32_t so = swoff(row, j);
                cpasync16(s0 + so,          Ah + ga + j * 8);
                cpasync16(s0 + OFF_AL + so, Al + ga + j * 8);
                cpasync16(s0 + OFF_BH + so, Bh + gb + j * 8);
                cpasync16(s0 + OFF_BL + so, Bl + gb + j * 8);
            }
        }
    };

    issue(0); asm volatile("cp.async.commit_group;");
    issue(1); asm volatile("cp.async.commit_group;");

    for (int c = 0; c < nC; c++) {
        asm volatile("cp.async.wait_group 1;");
        __syncthreads();
        if (c + 2 < nC) issue(c + 2);
        asm volatile("cp.async.commit_group;");

        const uint32_t s0 = sb + (c % NSTAGE) * STAGE_;
        #pragma unroll
        for (int ks = 0; ks < 2; ks++) {
            uint32_t a[4][4], b_h[8][2], b_l[8][2];
            #pragma unroll
            for (int i = 0; i < 4; i++) {
                const int row = wm * 64 + i * 16 + (lane & 15);
                const int ch  = 2 * ks + (lane >> 4);
                ldmx4(a[i][0], a[i][1], a[i][2], a[i][3], s0 + swoff(row, ch));
            }
            #pragma unroll
            for (int p = 0; p < 4; p++) {
                const int row = wn * 64 + p * 16 + (lane & 7) + ((lane & 16) >> 1);
                const int ch  = 2 * ks + ((lane >> 3) & 1);
                const uint32_t off = swoff(row, ch);
                uint32_t r0, r1, r2, r3;
                ldmx4(r0, r1, r2, r3, s0 + OFF_BH + off);
                b_h[2 * p][0] = r0; b_h[2 * p][1] = r1;
                b_h[2 * p + 1][0] = r2; b_h[2 * p + 1][1] = r3;
                ldmx4(r0, r1, r2, r3, s0 + OFF_BL + off);
                b_l[2 * p][0] = r0; b_l[2 * p][1] = r1;
                b_l[2 * p + 1][0] = r2; b_l[2 * p + 1][1] = r3;
            }
            #pragma unroll
            for (int i = 0; i < 4; i++)
                #pragma unroll
                for (int j = 0; j < 8; j++)
                    mma16816(acc[i][j], a[i], b_h[j]);
            #pragma unroll
            for (int i = 0; i < 4; i++)
                #pragma unroll
                for (int j = 0; j < 8; j++)
                    mma16816(acc[i][j], a[i], b_l[j]);
            #pragma unroll
            for (int i = 0; i < 4; i++) {
                const int row = wm * 64 + i * 16 + (lane & 15);
                const int ch  = 2 * ks + (lane >> 4);
                ldmx4(a[i][0], a[i][1], a[i][2], a[i][3], s0 + OFF_AL + swoff(row, ch));
            }
            #pragma unroll
            for (int i = 0; i < 4; i++)
                #pragma unroll
                for (int j = 0; j < 8; j++)
                    mma16816(acc[i][j], a[i], b_h[j]);
        }
    }

    const int r0 = by * BM + wm * 64 + (lane >> 2);
    const int c0 = bx * BN + wn * 64 + (lane & 3) * 2;
    #pragma unroll
    for (int i = 0; i < 4; i++)
        #pragma unroll
        for (int j = 0; j < 8; j++) {
            #pragma unroll
            for (int h = 0; h < 2; h++) {
                const float v0 = acc[i][j][2 * h], v1 = acc[i][j][2 * h + 1];
                const size_t o = (size_t)(r0 + i * 16 + 8 * h) * ldc + c0 + j * 8;
                __half h0 = __float2half_rn(v0), h1 = __float2half_rn(v1);
                __half l0 = __float2half_rn(v0 - __half2float(h0));
                __half l1 = __float2half_rn(v1 - __half2float(h1));
                *(__half2*)(Ch + o) = __halves2half2(h0, h1);
                *(__half2*)(Cl + o) = __halves2half2(l0, l1);
            }
        }
}

// ============ screening GEMM: fp16 accumulate, 256 thr, warp 64x32, triangular 1D grid ============
__global__ __launch_bounds__(256, 2)
void tgemm_screen(const __half* __restrict__ Ah, const __half* __restrict__ Bh,
                  __half* __restrict__ C, int K, int lda, int ldb, int ldc)
{
    const int t = blockIdx.x;
    int by = (int)((sqrtf(8.f * (float)t + 1.f) - 1.f) * 0.5f);
    while ((by + 1) * (by + 2) / 2 <= t) by++;
    while (by * (by + 1) / 2 > t) by--;
    const int bx = t - by * (by + 1) / 2;

    const int nC = K / BK;
    constexpr int STAGE_ = 2 * TILE_B;
    constexpr int OFF_B = TILE_B;

    extern __shared__ __align__(1024) char smem[];
    const uint32_t sb = sm_addr(smem);

    const int tid = threadIdx.x;
    const int lane = tid & 31, wid = tid >> 5;
    const int wm = wid & 1, wn = wid >> 1;

    const int lrow = tid >> 1;
    const int ljb  = (tid & 1) * 2;
    const size_t arow = (size_t)(by * BM + lrow) * lda;
    const size_t brow = (size_t)(bx * BN + lrow) * ldb;

    uint32_t acc[4][4][2];
    #pragma unroll
    for (int i = 0; i < 4; i++)
        #pragma unroll
        for (int j = 0; j < 4; j++) { acc[i][j][0] = 0u; acc[i][j][1] = 0u; }

    auto issue = [&](int c) {
        const uint32_t s0 = sb + (c % NSTAGE) * STAGE_;
        const int kc = c * BK;
        #pragma unroll
        for (int jj = 0; jj < 2; jj++) {
            const int j = ljb + jj;
            const uint32_t so = swoff(lrow, j);
            cpasync16(s0 + so,         Ah + arow + kc + j * 8);
            cpasync16(s0 + OFF_B + so, Bh + brow + kc + j * 8);
        }
    };

    issue(0); asm volatile("cp.async.commit_group;");
    issue(1); asm volatile("cp.async.commit_group;");

    for (int c = 0; c < nC; c++) {
        asm volatile("cp.async.wait_group 1;");
        __syncthreads();
        if (c + 2 < nC) issue(c + 2);
        asm volatile("cp.async.commit_group;");

        const uint32_t s0 = sb + (c % NSTAGE) * STAGE_;
        #pragma unroll
        for (int ks = 0; ks < 2; ks++) {
            uint32_t a[4][4], b_h[4][2];
            #pragma unroll
            for (int i = 0; i < 4; i++) {
                const int row = wm * 64 + i * 16 + (lane & 15);
                const int ch  = 2 * ks + (lane >> 4);
                ldmx4(a[i][0], a[i][1], a[i][2], a[i][3], s0 + swoff(row, ch));
            }
            #pragma unroll
            for (int p = 0; p < 2; p++) {
                const int row = wn * 32 + p * 16 + (lane & 7) + ((lane & 16) >> 1);
                const int ch  = 2 * ks + ((lane >> 3) & 1);
                uint32_t r0, r1, r2, r3;
                ldmx4(r0, r1, r2, r3, s0 + OFF_B + swoff(row, ch));
                b_h[2 * p][0] = r0; b_h[2 * p][1] = r1;
                b_h[2 * p + 1][0] = r2; b_h[2 * p + 1][1] = r3;
            }
            #pragma unroll
            for (int i = 0; i < 4; i++)
                #pragma unroll
                for (int j = 0; j < 4; j++)
                    mma16816h(acc[i][j], a[i], b_h[j]);
        }
    }

    const int r0 = by * BM + wm * 64 + (lane >> 2);
    const int c0 = bx * BN + wn * 32 + (lane & 3) * 2;
    #pragma unroll
    for (int i = 0; i < 4; i++)
        #pragma unroll
        for (int j = 0; j < 4; j++) {
            #pragma unroll
            for (int h = 0; h < 2; h++) {
                const size_t o = (size_t)(r0 + i * 16 + 8 * h) * ldc + c0 + j * 8;
                *(uint32_t*)(C + o) = acc[i][j][h];
            }
        }
}

// ============ 1-pass fp32-acc GEMM (output projection): 256 thr, warp 64x32 ============
__global__ __launch_bounds__(256, 2)
void tgemm1(const __half* __restrict__ Ah, const __half* __restrict__ Bh,
            float* __restrict__ Cf, int K, int lda, int ldb, int ldc)
{
    const int bx = blockIdx.x, by = blockIdx.y;
    const int nC = K / BK;
    constexpr int STAGE_ = 2 * TILE_B;
    constexpr int OFF_B = TILE_B;

    extern __shared__ __align__(1024) char smem[];
    const uint32_t sb = sm_addr(smem);

    const int tid = threadIdx.x;
    const int lane = tid & 31, wid = tid >> 5;
    const int wm = wid & 1, wn = wid >> 1;

    const int lrow = tid >> 1;
    const int ljb  = (tid & 1) * 2;
    const size_t arow = (size_t)(by * BM + lrow) * lda;
    const size_t brow = (size_t)(bx * BN + lrow) * ldb;

    float acc[4][4][4];
    #pragma unroll
    for (int i = 0; i < 4; i++)
        #pragma unroll
        for (int j = 0; j < 4; j++)
            #pragma unroll
            for (int r = 0; r < 4; r++) acc[i][j][r] = 0.f;

    auto issue = [&](int c) {
        const uint32_t s0 = sb + (c % NSTAGE) * STAGE_;
        const int kc = c * BK;
        #pragma unroll
        for (int jj = 0; jj < 2; jj++) {
            const int j = ljb + jj;
            const uint32_t so = swoff(lrow, j);
            cpasync16(s0 + so,         Ah + arow + kc + j * 8);
            cpasync16(s0 + OFF_B + so, Bh + brow + kc + j * 8);
        }
    };

    issue(0); asm volatile("cp.async.commit_group;");
    issue(1); asm volatile("cp.async.commit_group;");

    for (int c = 0; c < nC; c++) {
        asm volatile("cp.async.wait_group 1;");
        __syncthreads();
        if (c + 2 < nC) issue(c + 2);
        asm volatile("cp.async.commit_group;");

        const uint32_t s0 = sb + (c % NSTAGE) * STAGE_;
        #pragma unroll
        for (int ks = 0; ks < 2; ks++) {
            uint32_t a[4][4], b_h[4][2];
            #pragma unroll
            for (int i = 0; i < 4; i++) {
                const int row = wm * 64 + i * 16 + (lane & 15);
                const int ch  = 2 * ks + (lane >> 4);
                ldmx4(a[i][0], a[i][1], a[i][2], a[i][3], s0 + swoff(row, ch));
            }
            #pragma unroll
            for (int p = 0; p < 2; p++) {
                const int row = wn * 32 + p * 16 + (lane & 7) + ((lane & 16) >> 1);
                const int ch  = 2 * ks + ((lane >> 3) & 1);
                uint32_t r0, r1, r2, r3;
                ldmx4(r0, r1, r2, r3, s0 + OFF_B + swoff(row, ch));
                b_h[2 * p][0] = r0; b_h[2 * p][1] = r1;
                b_h[2 * p + 1][0] = r2; b_h[2 * p + 1][1] = r3;
            }
            #pragma unroll
            for (int i = 0; i < 4; i++)
                #pragma unroll
                for (int j = 0; j < 4; j++)
                    mma16816(acc[i][j], a[i], b_h[j]);
        }
    }

    const int r0 = by * BM + wm * 64 + (lane >> 2);
    const int c0 = bx * BN + wn * 32 + (lane & 3) * 2;
    #pragma unroll
    for (int i = 0; i < 4; i++)
        #pragma unroll
        for (int j = 0; j < 4; j++) {
            #pragma unroll
            for (int h = 0; h < 2; h++) {
                const size_t o = (size_t)(r0 + i * 16 + 8 * h) * ldc + c0 + j * 8;
                *(float2*)(Cf + o) = make_float2(acc[i][j][2 * h], acc[i][j][2 * h + 1]);
            }
        }
}

// ---------------- fused fp32 -> fp16 hi/lo splits ----------------
__global__ __launch_bounds__(256)
void splitk_all(const float* __restrict__ x,   __half* __restrict__ xh, __half* __restrict__ xl,
                const float* __restrict__ wq,  __half* __restrict__ wqh, __half* __restrict__ wql,
                const float* __restrict__ wv,  __half* __restrict__ wvh)
{
    const int nx = NCTX * DMODEL, nw = DMODEL * DMODEL;
    int i = (blockIdx.x * 256 + threadIdx.x) * 4;
    const float* in; __half* h; __half* l;
    if (i < nx)               { in = x;  h = xh;  l = xl;  }
    else if (i < nx + nw)     { in = wq; h = wqh; l = wql; i -= nx; }
    else if (i < nx + 2 * nw) { in = wv; h = wvh; l = nullptr; i -= nx + nw; }
    else return;

    float4 v = *(const float4*)(in + i);
    __half h0 = __float2half_rn(v.x), h1 = __float2half_rn(v.y);
    __half h2 = __float2half_rn(v.z), h3 = __float2half_rn(v.w);
    *(__half2*)(h + i)     = __halves2half2(h0, h1);
    *(__half2*)(h + i + 2) = __halves2half2(h2, h3);
    if (l) {
        __half l0 = __float2half_rn(v.x - __half2float(h0));
        __half l1 = __float2half_rn(v.y - __half2float(h1));
        __half l2 = __float2half_rn(v.z - __half2float(h2));
        __half l3 = __float2half_rn(v.w - __half2float(h3));
        *(__half2*)(l + i)     = __halves2half2(l0, l1);
        *(__half2*)(l + i + 2) = __halves2half2(l2, l3);
    }
}

// ---------------- reductions ----------------
__device__ __forceinline__ float warpMax(float v) {
    #pragma unroll
    for (int o = 16; o; o >>= 1) v = fmaxf(v, __shfl_xor_sync(0xffffffffu, v, o));
    return v;
}
__device__ __forceinline__ float warpSum(float v) {
    #pragma unroll
    for (int o = 16; o; o >>= 1) v += __shfl_xor_sync(0xffffffffu, v, o);
    return v;
}

// ---------------- fused screening softmax + exact rescore + AV ----------------
// Restructured for latency: 4 barriers total, uint16 candidate indices (32KB
// smem -> 7 blocks/SM), q-row prefetch overlapped with score read, approx max
// used as the global exp shift (shift-invariant; exponents in [-21, +1]),
// normalization folded into the AV epilogue.
__global__ __launch_bounds__(256)
void softmax_av_fused(const __half* __restrict__ S, const __half* __restrict__ Qh,
                      const __half* __restrict__ Ql, const float* __restrict__ x,
                      __half* __restrict__ Zh, int N)
{
    const int row = blockIdx.x;
    const int len = row + 1;
    const __half* Srow = S + (size_t)row * N;
    const int tid = threadIdx.x;
    const int lane = tid & 31, wid = tid >> 5;

    __shared__ float red[8];
    __shared__ float red2[8];
    __shared__ int scnt;
    __shared__ uint16_t cidx[NCTX];     // 8 KB
    __shared__ float    csc[NCTX];      // 16 KB
    __shared__ float    qs[DMODEL];     // 8 KB
    if (tid == 0) scnt = 0;

    // Prefetch q row into smem first (LDGs overlap with the score read below)
    const __half* qhr = Qh + (size_t)row * DMODEL;
    const __half* qlr = Ql + (size_t)row * DMODEL;
    #pragma unroll
    for (int k = 0; k < DMODEL / 256; k++) {
        const int idx = tid + k * 256;
        qs[idx] = __half2float(qhr[idx]) + __half2float(qlr[idx]);
    }

    // A: vectorized score read (2 x 8 halves per thread), cached in registers
    float vals[2][8];
    float m = -3.4e38f;
    #pragma unroll
    for (int k = 0; k < 2; k++) {
        const int base = tid * 8 + k * 2048;
        if (base < len) {
            const uint4 u = *(const uint4*)(Srow + base);
            const __half2* hp = (const __half2*)&u;
            #pragma unroll
            for (int e = 0; e < 4; e++) {
                const float2 f = __half22float2(hp[e]);
                vals[k][2 * e]     = (base + 2 * e     < len) ? f.x : -3.4e38f;
                vals[k][2 * e + 1] = (base + 2 * e + 1 < len) ? f.y : -3.4e38f;
            }
            #pragma unroll
            for (int e = 0; e < 8; e++) m = fmaxf(m, vals[k][e]);
        } else {
            #pragma unroll
            for (int e = 0; e < 8; e++) vals[k][e] = -3.4e38f;
        }
    }
    m = warpMax(m);
    if (lane == 0) red[wid] = m;
    __syncthreads();                                   // [1] red + scnt init
    float ma = red[0];
    #pragma unroll
    for (int w = 1; w < 8; w++) ma = fmaxf(ma, red[w]);

    // B: collect candidates + approximate tail mass (all relative to ma)
    const float thr = ma - 20.0f;
    float tail = 0.f;
    #pragma unroll
    for (int k = 0; k < 2; k++) {
        #pragma unroll
        for (int e = 0; e < 8; e++) {
            const float v = vals[k][e];
            if (v > thr) {
                const int slot = atomicAdd(&scnt, 1);
                cidx[slot] = (uint16_t)(tid * 8 + k * 2048 + e);
            } else if (v > -1e37f) {
                tail += __expf(v - ma);
            }
        }
    }
    tail = warpSum(tail);
    if (lane == 0) red2[wid] = tail;
    __syncthreads();                                   // [2] cidx/scnt/qs/red2
    float tsum = 0.f;
    #pragma unroll
    for (int w = 0; w < 8; w++) tsum += red2[w];

    // D: exact rescoring, one warp per candidate; store e = exp(p - ma)
    const int nc = scnt;
    for (int c = wid; c < nc; c += 8) {
        const float* xr = x + (size_t)cidx[c] * DMODEL;
        float p0 = 0.f, p1 = 0.f;
        #pragma unroll 4
        for (int k = lane; k < DMODEL; k += 64) {
            p0 = fmaf(qs[k], xr[k], p0);
            p1 = fmaf(qs[k + 32], xr[k + 32], p1);
        }
        float p = warpSum(p0 + p1);
        if (lane == 0) csc[c] = __expf(p - ma);
    }
    __syncthreads();                                   // [3] csc complete

    // F: Z = tail + sum of candidate exps
    float zs = 0.f;
    for (int c = tid; c < nc; c += 256) zs += csc[c];
    zs = warpSum(zs);
    if (lane == 0) red[wid] = zs;
    __syncthreads();                                   // [4] red
    float Z = tsum;
    #pragma unroll
    for (int w = 0; w < 8; w++) Z += red[w];
    const float inv = 1.0f / Z;

    // H: z = (sum_j e_j * x_j) * inv  (each thread owns 8 dims)
    float acc[8];
    #pragma unroll
    for (int r = 0; r < 8; r++) acc[r] = 0.f;
    const int d0 = tid * 8;
    #pragma unroll 2
    for (int c = 0; c < nc; c++) {
        const float w = csc[c];
        const float* xr = x + (size_t)cidx[c] * DMODEL + d0;
        const float4 a = *(const float4*)xr;
        const float4 b = *(const float4*)(xr + 4);
        acc[0] = fmaf(w, a.x, acc[0]); acc[1] = fmaf(w, a.y, acc[1]);
        acc[2] = fmaf(w, a.z, acc[2]); acc[3] = fmaf(w, a.w, acc[3]);
        acc[4] = fmaf(w, b.x, acc[4]); acc[5] = fmaf(w, b.y, acc[5]);
        acc[6] = fmaf(w, b.z, acc[6]); acc[7] = fmaf(w, b.w, acc[7]);
    }

    __half* zh = Zh + (size_t)row * DMODEL + d0;
    #pragma unroll
    for (int r = 0; r < 8; r += 2)
        *(__half2*)(zh + r) = __halves2half2(__float2half_rn(acc[r] * inv),
                                             __float2half_rn(acc[r + 1] * inv));
}

// ---------------- host ----------------
extern "C" void kernel_launch(void* const* d_in, const int* in_sizes, int n_in,
                              void* d_out, int out_size)
{
    const float* x   = (const float*)d_in[0];
    const float* Wqk = (const float*)d_in[1];
    const float* Wov = (const float*)d_in[2];
    float* out = (float*)d_out;

    __half* s; cudaGetSymbolAddress((void**)&s, g_s);
    __half *xh, *xl, *wqh, *wql, *wvh, *qh, *ql, *zh;
    cudaGetSymbolAddress((void**)&xh,  g_xh);  cudaGetSymbolAddress((void**)&xl,  g_xl);
    cudaGetSymbolAddress((void**)&wqh, g_wqh); cudaGetSymbolAddress((void**)&wql, g_wql);
    cudaGetSymbolAddress((void**)&wvh, g_wvh);
    cudaGetSymbolAddress((void**)&qh,  g_qh);  cudaGetSymbolAddress((void**)&ql,  g_ql);
    cudaGetSymbolAddress((void**)&zh,  g_zh);

    cudaFuncSetAttribute(tgemm3, cudaFuncAttributeMaxDynamicSharedMemorySize, SMEM3);
    cudaFuncSetAttribute(tgemm_screen, cudaFuncAttributeMaxDynamicSharedMemorySize, SMEM1);
    cudaFuncSetAttribute(tgemm1, cudaFuncAttributeMaxDynamicSharedMemorySize, SMEM1);

    const int nx = NCTX * DMODEL, nw = DMODEL * DMODEL;
    const int ntot = nx + 2 * nw;

    // 0) all input splits in one launch
    splitk_all<<<ntot / 1024, 256>>>(x, xh, xl, Wqk, wqh, wql, Wov, wvh);

    // 1) q = x @ Wqk^T -> q hi/lo (3-pass, 4-warp 64x64 kernel)
    tgemm3<<<dim3(DMODEL / BN, NCTX / BM), 128, SMEM3>>>(
        xh, xl, wqh, wql, qh, ql, DMODEL, DMODEL, DMODEL, DMODEL);

    // 2) s~ = qh @ xh^T (fp16-acc screening, triangular 1D grid) -> fp16 scores
    const int ntri = (NCTX / BM) * (NCTX / BM + 1) / 2;    // 528
    tgemm_screen<<<ntri, 256, SMEM1>>>(qh, xh, s, DMODEL, DMODEL, DMODEL, NCTX);

    // 3) fused screening softmax + exact rescore + AV -> z (fp16)
    softmax_av_fused<<<NCTX, 256>>>(s, qh, ql, x, zh, NCTX);

    // 4) out = zh @ Wovh^T (1-pass fp32 acc) -> fp32 output
    tgemm1<<<dim3(DMODEL / BN, NCTX / BM), 256, SMEM1>>>(
        zh, wvh, out, DMODEL, DMODEL, DMODEL, DMODEL);
}